// round 3
// baseline (speedup 1.0000x reference)
#include <cuda_runtime.h>
#include <math.h>

#define S_LEN 16
#define BSZ   64
#define NN    10000
#define LL    128
#define DMSG  129
#define DH    257
#define SCALE 0.08838834764831844f  // 1/sqrt(128)
#define TILE_N 50

// ---------------- scratch (device globals; no allocation allowed) -------------
__device__ float g_mem[NN * LL];          // node memory (N,L)
__device__ float g_newh[2 * BSZ * LL];    // GRU outputs: [src rows 0..63][tgt rows 64..127]
__device__ float g_ck[BSZ * DH];          // scale * (Wk @ q[b])
__device__ float g_qbk[BSZ];              // scale * (q[b] . bk)
__device__ float g_scores[BSZ * NN];
__device__ float g_pv[BSZ * NN];          // dt-part of value per (b,n)
__device__ float g_memdot[NN];            // mem[n] . cv_mem
__device__ float g_cv[DH];                // Wv @ W_out
__device__ float g_cvc;                   // bv.W_out + b_out
__device__ float g_enc0[LL];              // cos(time_b)

// ---------------- K0a: zero memory --------------------------------------------
__global__ void k_zero_mem() {
    int i = blockIdx.x * blockDim.x + threadIdx.x;
    if (i < NN * LL) g_mem[i] = 0.0f;
}

// ---------------- K0b: step-invariant precompute -------------------------------
__global__ void k_init(const float* __restrict__ Wv, const float* __restrict__ W_out,
                       const float* __restrict__ bv, const float* __restrict__ b_out,
                       const float* __restrict__ time_b) {
    int tid = threadIdx.x;
    if (tid < DH) {
        float a = 0.0f;
        const float* wr = Wv + tid * LL;
        for (int l = 0; l < LL; l++) a = fmaf(wr[l], W_out[l], a);
        g_cv[tid] = a;
    }
    if (tid < LL) g_enc0[tid] = cosf(time_b[tid]);
    if (tid == 280) {
        float a = 0.0f;
        for (int l = 0; l < LL; l++) a = fmaf(bv[l], W_out[l], a);
        g_cvc = a + b_out[0];
    }
}

// ---------------- K1a: GRU for 128 cells (64 src + 64 tgt), uses OLD memory ----
__global__ void k_gru(const float* __restrict__ x, const float* __restrict__ t,
                      const int* __restrict__ src, const int* __restrict__ tgt,
                      const float* __restrict__ time_w, const float* __restrict__ time_b,
                      const float* __restrict__ W_ih, const float* __restrict__ W_hh,
                      const float* __restrict__ b_ih, const float* __restrict__ b_hh,
                      int s) {
    __shared__ float s_msg[DMSG];
    __shared__ float s_h[LL];
    __shared__ float s_sum[2 * LL];
    __shared__ float s_in[LL];
    __shared__ float s_hn[LL];

    int cell = blockIdx.x;          // 0..127
    int b = cell & 63;
    int is_t = cell >> 6;
    int node = (is_t ? tgt : src)[s * BSZ + b];
    long base = ((long)(s * BSZ + b)) * NN + node;
    int tid = threadIdx.x;          // 384 threads

    if (tid < LL) {
        s_h[tid] = g_mem[node * LL + tid];
        float tv = t[base];
        s_msg[1 + tid] = cosf(fmaf(tv, time_w[tid], time_b[tid]));
    }
    if (tid == 128) s_msg[0] = x[base];
    __syncthreads();

    {
        int j = tid; // 0..383
        float gi = b_ih[j];
        const float* wr = W_ih + j * DMSG;
        for (int d = 0; d < DMSG; d++) gi = fmaf(__ldg(wr + d), s_msg[d], gi);
        float gh = b_hh[j];
        const float* hr = W_hh + j * LL;
        for (int l = 0; l < LL; l++) gh = fmaf(__ldg(hr + l), s_h[l], gh);
        if (j < 2 * LL) s_sum[j] = gi + gh;
        else { s_in[j - 2 * LL] = gi; s_hn[j - 2 * LL] = gh; }
    }
    __syncthreads();

    if (tid < LL) {
        float r = 1.0f / (1.0f + expf(-s_sum[tid]));
        float z = 1.0f / (1.0f + expf(-s_sum[LL + tid]));
        float nn = tanhf(fmaf(r, s_hn[tid], s_in[tid]));
        // (1-z)*n + z*h = n + z*(h-n)
        g_newh[cell * LL + tid] = fmaf(z, s_h[tid] - nn, nn);
    }
}

// ---------------- K1b: ordered scatter (src pass then tgt pass; last b wins) ---
__global__ void k_scatter(const int* __restrict__ src, const int* __restrict__ tgt, int s) {
    int tid = threadIdx.x;  // 128 — thread owns lane l; per-thread program order
    for (int b = 0; b < BSZ; b++) {
        int node = src[s * BSZ + b];
        g_mem[node * LL + tid] = g_newh[b * LL + tid];
    }
    for (int b = 0; b < BSZ; b++) {
        int node = tgt[s * BSZ + b];
        g_mem[node * LL + tid] = g_newh[(BSZ + b) * LL + tid];
    }
}

// ---------------- K1c: q[b] then ck[b] = scale * Wk@q, qbk -----------------------
__global__ void k_qck(const float* __restrict__ x, const int* __restrict__ tgt,
                      const float* __restrict__ Wq, const float* __restrict__ bq,
                      const float* __restrict__ Wk, const float* __restrict__ bk, int s) {
    __shared__ float s_th[DH];
    __shared__ float s_q[LL];
    int b = blockIdx.x;
    int tid = threadIdx.x;  // 256
    int node = tgt[s * BSZ + b];
    if (tid == 0) s_th[0] = x[((long)(s * BSZ + b)) * NN + node];
    if (tid < LL) {
        s_th[1 + tid] = g_mem[node * LL + tid];   // post-scatter memory
        s_th[1 + LL + tid] = g_enc0[tid];
    }
    __syncthreads();
    if (tid < LL) {
        float q = bq[tid];
        for (int d = 0; d < DH; d++) q = fmaf(s_th[d], __ldg(Wq + d * LL + tid), q);
        s_q[tid] = q;
    }
    __syncthreads();
    for (int d = tid; d < DH; d += blockDim.x) {
        float a = 0.0f;
        const float* wr = Wk + d * LL;
        for (int l = 0; l < LL; l++) a = fmaf(__ldg(wr + l), s_q[l], a);
        g_ck[b * DH + d] = SCALE * a;
    }
    if (tid == 0) {
        float a = 0.0f;
        for (int l = 0; l < LL; l++) a = fmaf(s_q[l], bk[l], a);
        g_qbk[b] = SCALE * a;
    }
}

// ---------------- K2: scores + pv + memdot (the heavy one) ----------------------
__global__ void __launch_bounds__(256) k_scores(
        const float* __restrict__ x, const float* __restrict__ t,
        const int* __restrict__ mask,
        const float* __restrict__ time_w, const float* __restrict__ time_b, int s) {
    __shared__ float s_mem[TILE_N * LL];  // 25.6KB
    int n0 = blockIdx.x * TILE_N;
    int tid = threadIdx.x;

    for (int i = tid; i < TILE_N * LL; i += 256) s_mem[i] = g_mem[n0 * LL + i];
    __syncthreads();

    int warp = tid >> 5, lane = tid & 31;
    int b = blockIdx.y * 8 + warp;

    float tw[4], tc[4], ckd[4], ckm[4], cvd[4];
#pragma unroll
    for (int j = 0; j < 4; j++) {
        int l = j * 32 + lane;
        tw[j]  = time_w[l];
        tc[j]  = time_b[l];
        ckd[j] = g_ck[b * DH + 1 + LL + l];
        ckm[j] = g_ck[b * DH + 1 + l];
        cvd[j] = g_cv[1 + LL + l];
    }
    float ck0 = g_ck[b * DH];
    float qbk = g_qbk[b];
    long base = ((long)(s * BSZ + b)) * NN;

    if (blockIdx.y == 0) {
        // memdot for this n-tile (b-independent)
        float cvm[4];
#pragma unroll
        for (int j = 0; j < 4; j++) cvm[j] = g_cv[1 + j * 32 + lane];
        for (int r = warp; r < TILE_N; r += 8) {
            float a = 0.0f;
#pragma unroll
            for (int j = 0; j < 4; j++) a = fmaf(cvm[j], s_mem[r * LL + j * 32 + lane], a);
#pragma unroll
            for (int o = 16; o; o >>= 1) a += __shfl_xor_sync(0xffffffffu, a, o);
            if (lane == 0) g_memdot[n0 + r] = a;
        }
    }

    for (int r = 0; r < TILE_N; r++) {
        int n = n0 + r;
        float tv = __ldg(t + base + n);
        float sp = 0.0f, pp = 0.0f;
        const float* mr = s_mem + r * LL;
#pragma unroll
        for (int j = 0; j < 4; j++) {
            float cw = __cosf(fmaf(tv, tw[j], tc[j]));
            sp = fmaf(ckd[j], cw, sp);
            pp = fmaf(cvd[j], cw, pp);
            sp = fmaf(ckm[j], mr[j * 32 + lane], sp);
        }
#pragma unroll
        for (int o = 16; o; o >>= 1) {
            sp += __shfl_xor_sync(0xffffffffu, sp, o);
            pp += __shfl_xor_sync(0xffffffffu, pp, o);
        }
        if (lane == 0) {
            float xv = __ldg(x + base + n);
            float sc = fmaf(ck0, xv, sp) + qbk;
            int m = __ldg(mask + base + n);              // bool exported as int32
            g_scores[b * NN + n] = m ? sc : -1e9f;
            g_pv[b * NN + n] = pp;
        }
    }
}

// ---------------- K3: softmax + logit -------------------------------------------
__global__ void k_softmax(const float* __restrict__ x, float* __restrict__ out, int s) {
    __shared__ float s_red[256];
    int b = blockIdx.x, tid = threadIdx.x;
    const float* sc = g_scores + b * NN;
    const float* pv = g_pv + b * NN;
    long base = ((long)(s * BSZ + b)) * NN;
    float cv0 = g_cv[0];

    float mx = -3e38f;
    for (int i = tid; i < NN; i += 256) mx = fmaxf(mx, sc[i]);
    s_red[tid] = mx; __syncthreads();
    for (int o = 128; o; o >>= 1) { if (tid < o) s_red[tid] = fmaxf(s_red[tid], s_red[tid + o]); __syncthreads(); }
    mx = s_red[0]; __syncthreads();

    float Z = 0.0f, V = 0.0f;
    for (int i = tid; i < NN; i += 256) {
        float e = __expf(sc[i] - mx);
        Z += e;
        float val = fmaf(cv0, __ldg(x + base + i), g_memdot[i] + pv[i]);
        V = fmaf(e, val, V);
    }
    s_red[tid] = Z; __syncthreads();
    for (int o = 128; o; o >>= 1) { if (tid < o) s_red[tid] += s_red[tid + o]; __syncthreads(); }
    Z = s_red[0]; __syncthreads();
    s_red[tid] = V; __syncthreads();
    for (int o = 128; o; o >>= 1) { if (tid < o) s_red[tid] += s_red[tid + o]; __syncthreads(); }
    if (tid == 0) out[s * BSZ + b] = s_red[0] / Z + g_cvc;
}

// ---------------- host -----------------------------------------------------------
extern "C" void kernel_launch(void* const* d_in, const int* in_sizes, int n_in,
                              void* d_out, int out_size) {
    const float* x       = (const float*)d_in[0];
    const float* t       = (const float*)d_in[1];
    const int*   src     = (const int*)d_in[2];
    const int*   tgt     = (const int*)d_in[3];
    const int*   mask    = (const int*)d_in[4];
    const float* time_w  = (const float*)d_in[5];
    const float* time_b  = (const float*)d_in[6];
    const float* W_ih    = (const float*)d_in[7];
    const float* W_hh    = (const float*)d_in[8];
    const float* b_ih    = (const float*)d_in[9];
    const float* b_hh    = (const float*)d_in[10];
    const float* Wq      = (const float*)d_in[11];
    const float* bq      = (const float*)d_in[12];
    const float* Wk      = (const float*)d_in[13];
    const float* bk      = (const float*)d_in[14];
    const float* Wv      = (const float*)d_in[15];
    const float* bv      = (const float*)d_in[16];
    const float* W_out   = (const float*)d_in[17];
    const float* b_out   = (const float*)d_in[18];
    float* out = (float*)d_out;

    k_zero_mem<<<(NN * LL + 255) / 256, 256>>>();
    k_init<<<1, 288>>>(Wv, W_out, bv, b_out, time_b);

    for (int s = 0; s < S_LEN; s++) {
        k_gru<<<128, 384>>>(x, t, src, tgt, time_w, time_b, W_ih, W_hh, b_ih, b_hh, s);
        k_scatter<<<1, 128>>>(src, tgt, s);
        k_qck<<<64, 256>>>(x, tgt, Wq, bq, Wk, bk, s);
        k_scores<<<dim3(NN / TILE_N, 8), 256>>>(x, t, mask, time_w, time_b, s);
        k_softmax<<<64, 256>>>(x, out, s);
    }
}

// round 4
// speedup vs baseline: 1.6861x; 1.6861x over previous
#include <cuda_runtime.h>
#include <math.h>

#define S_LEN 16
#define BSZ   64
#define NN    10000
#define LL    128
#define DMSG  129
#define DH    257
#define SCALE 0.08838834764831844f  // 1/sqrt(128)
#define TILE_N 50

// ---------------- scratch (device globals; no allocation allowed) -------------
__device__ float g_mem[NN * LL];          // node memory (N,L)
__device__ float g_newh[2 * BSZ * LL];    // GRU outputs: [src rows 0..63][tgt rows 64..127]
__device__ float g_ck[BSZ * DH];          // scale * (Wk @ q[b])
__device__ float g_qbk[BSZ];              // scale * (q[b] . bk)
__device__ float g_scores[BSZ * NN];
__device__ float g_pv[BSZ * NN];          // dt-part of value per (b,n)
__device__ float g_memdot[NN];            // mem[n] . cv_mem (maintained incrementally)
__device__ float g_cv[DH];                // Wv @ W_out
__device__ float g_cvc;                   // bv.W_out + b_out
__device__ float g_enc0[LL];              // cos(time_b)

// ---------------- K0a: zero memory + memdot ------------------------------------
__global__ void k_zero_mem() {
    int i = blockIdx.x * blockDim.x + threadIdx.x;
    if (i < NN * LL) g_mem[i] = 0.0f;
    if (i < NN) g_memdot[i] = 0.0f;
}

// ---------------- K0b: step-invariant precompute -------------------------------
__global__ void k_init(const float* __restrict__ Wv, const float* __restrict__ W_out,
                       const float* __restrict__ bv, const float* __restrict__ b_out,
                       const float* __restrict__ time_b) {
    int tid = threadIdx.x;
    if (tid < DH) {
        float a = 0.0f;
        const float* wr = Wv + tid * LL;
        for (int l = 0; l < LL; l++) a = fmaf(wr[l], W_out[l], a);
        g_cv[tid] = a;
    }
    if (tid < LL) g_enc0[tid] = cosf(time_b[tid]);
    if (tid == 280) {
        float a = 0.0f;
        for (int l = 0; l < LL; l++) a = fmaf(bv[l], W_out[l], a);
        g_cvc = a + b_out[0];
    }
}

// ---------------- K1a: GRU, warp-per-output-row (coalesced W loads) ------------
__global__ void __launch_bounds__(384) k_gru(
        const float* __restrict__ x, const float* __restrict__ t,
        const int* __restrict__ src, const int* __restrict__ tgt,
        const float* __restrict__ time_w, const float* __restrict__ time_b,
        const float* __restrict__ W_ih, const float* __restrict__ W_hh,
        const float* __restrict__ b_ih, const float* __restrict__ b_hh,
        int s) {
    __shared__ float s_msg[DMSG];
    __shared__ float s_h[LL];
    __shared__ float s_sum[2 * LL];
    __shared__ float s_in[LL];
    __shared__ float s_hn[LL];

    int cell = blockIdx.x;          // 0..127
    int b = cell & 63;
    int is_t = cell >> 6;
    int node = (is_t ? tgt : src)[s * BSZ + b];
    long base = ((long)(s * BSZ + b)) * NN + node;
    int tid = threadIdx.x;          // 384 threads = 12 warps
    int warp = tid >> 5, lane = tid & 31;

    if (tid < LL) {
        s_h[tid] = g_mem[node * LL + tid];
        float tv = t[base];
        s_msg[1 + tid] = cosf(fmaf(tv, time_w[tid], time_b[tid]));
    }
    if (tid == 128) s_msg[0] = x[base];
    __syncthreads();

    // warp handles rows j = warp + 12*i  (i = 0..31) => j in [0,384)
    for (int i = 0; i < 32; i++) {
        int j = warp + 12 * i;
        float ai = 0.0f, ah = 0.0f;
        const float* wi = W_ih + j * DMSG;
        const float* wh = W_hh + j * LL;
#pragma unroll
        for (int ch = 0; ch < 5; ch++) {
            int d = ch * 32 + lane;
            if (d < DMSG) ai = fmaf(__ldg(wi + d), s_msg[d], ai);
        }
#pragma unroll
        for (int ch = 0; ch < 4; ch++) {
            int l = ch * 32 + lane;
            ah = fmaf(__ldg(wh + l), s_h[l], ah);
        }
#pragma unroll
        for (int o = 16; o; o >>= 1) {
            ai += __shfl_xor_sync(0xffffffffu, ai, o);
            ah += __shfl_xor_sync(0xffffffffu, ah, o);
        }
        if (lane == 0) {
            ai += b_ih[j];
            ah += b_hh[j];
            if (j < 2 * LL) s_sum[j] = ai + ah;
            else { s_in[j - 2 * LL] = ai; s_hn[j - 2 * LL] = ah; }
        }
    }
    __syncthreads();

    if (tid < LL) {
        float r = 1.0f / (1.0f + expf(-s_sum[tid]));
        float z = 1.0f / (1.0f + expf(-s_sum[LL + tid]));
        float nn = tanhf(fmaf(r, s_hn[tid], s_in[tid]));
        g_newh[cell * LL + tid] = fmaf(z, s_h[tid] - nn, nn);
    }
}

// ---------------- K1b: parallel scatter with winner vote + memdot update -------
// Order semantics: src b=0..63 then tgt b=0..63, last write wins.
__global__ void k_scatter(const int* __restrict__ src, const int* __restrict__ tgt, int s) {
    __shared__ int s_nodes[2 * BSZ];
    __shared__ float s_red[4];
    int c = blockIdx.x;             // cell 0..127
    int tid = threadIdx.x;          // 128

    s_nodes[tid] = (tid < BSZ) ? src[s * BSZ + tid] : tgt[s * BSZ + (tid - BSZ)];
    __syncthreads();
    int my = s_nodes[c];
    bool loser = (tid > c) && (s_nodes[tid] == my);
    if (__syncthreads_or(loser)) return;   // a later cell overwrites this node

    float v = g_newh[c * LL + tid];
    g_mem[my * LL + tid] = v;

    // incremental memdot: mem[my] . cv_mem
    float a = v * g_cv[1 + tid];
#pragma unroll
    for (int o = 16; o; o >>= 1) a += __shfl_xor_sync(0xffffffffu, a, o);
    if ((tid & 31) == 0) s_red[tid >> 5] = a;
    __syncthreads();
    if (tid == 0) g_memdot[my] = s_red[0] + s_red[1] + s_red[2] + s_red[3];
}

// ---------------- K1c: q[b] then ck[b] = scale * Wk@q, qbk -----------------------
__global__ void __launch_bounds__(256) k_qck(
        const float* __restrict__ x, const int* __restrict__ tgt,
        const float* __restrict__ Wq, const float* __restrict__ bq,
        const float* __restrict__ Wk, const float* __restrict__ bk, int s) {
    __shared__ float s_th[DH];
    __shared__ float s_q[LL];
    int b = blockIdx.x;
    int tid = threadIdx.x;  // 256 = 8 warps
    int warp = tid >> 5, lane = tid & 31;
    int node = tgt[s * BSZ + b];
    if (tid == 0) s_th[0] = x[((long)(s * BSZ + b)) * NN + node];
    if (tid < LL) {
        s_th[1 + tid] = g_mem[node * LL + tid];   // post-scatter memory
        s_th[1 + LL + tid] = g_enc0[tid];
    }
    __syncthreads();
    if (tid < LL) {
        // 4 accumulators to break the fma chain; Wq column access is coalesced
        float q0 = 0.f, q1 = 0.f, q2 = 0.f, q3 = 0.f;
        int d = 0;
        for (; d + 3 < DH; d += 4) {
            q0 = fmaf(s_th[d],     __ldg(Wq + (d    ) * LL + tid), q0);
            q1 = fmaf(s_th[d + 1], __ldg(Wq + (d + 1) * LL + tid), q1);
            q2 = fmaf(s_th[d + 2], __ldg(Wq + (d + 2) * LL + tid), q2);
            q3 = fmaf(s_th[d + 3], __ldg(Wq + (d + 3) * LL + tid), q3);
        }
        for (; d < DH; d++) q0 = fmaf(s_th[d], __ldg(Wq + d * LL + tid), q0);
        s_q[tid] = (q0 + q1) + (q2 + q3) + bq[tid];
    }
    __syncthreads();
    // ck: warp per output d (coalesced Wk row reads), 8 warps cover DH
    for (int d = warp; d < DH; d += 8) {
        float a = 0.0f;
        const float* wr = Wk + d * LL;
#pragma unroll
        for (int ch = 0; ch < 4; ch++) {
            int l = ch * 32 + lane;
            a = fmaf(__ldg(wr + l), s_q[l], a);
        }
#pragma unroll
        for (int o = 16; o; o >>= 1) a += __shfl_xor_sync(0xffffffffu, a, o);
        if (lane == 0) g_ck[b * DH + d] = SCALE * a;
    }
    if (tid == 0) {
        float a = 0.0f;
        for (int l = 0; l < LL; l++) a = fmaf(s_q[l], bk[l], a);
        g_qbk[b] = SCALE * a;
    }
}

// ---------------- K2: scores + pv with mask skip (the heavy one) ----------------
__global__ void __launch_bounds__(256) k_scores(
        const float* __restrict__ x, const float* __restrict__ t,
        const int* __restrict__ mask,
        const float* __restrict__ time_w, const float* __restrict__ time_b, int s) {
    __shared__ float s_mem[TILE_N * LL];  // 25.6KB
    int n0 = blockIdx.x * TILE_N;
    int tid = threadIdx.x;

    for (int i = tid; i < TILE_N * LL; i += 256) s_mem[i] = g_mem[n0 * LL + i];
    __syncthreads();

    int warp = tid >> 5, lane = tid & 31;
    int b = blockIdx.y * 8 + warp;

    float tw[4], tc[4], ckd[4], ckm[4], cvd[4];
#pragma unroll
    for (int j = 0; j < 4; j++) {
        int l = j * 32 + lane;
        tw[j]  = time_w[l];
        tc[j]  = time_b[l];
        ckd[j] = g_ck[b * DH + 1 + LL + l];
        ckm[j] = g_ck[b * DH + 1 + l];
        cvd[j] = g_cv[1 + LL + l];
    }
    float ck0 = g_ck[b * DH];
    float qbk = g_qbk[b];
    long base = ((long)(s * BSZ + b)) * NN;
    float* sc_row = g_scores + b * NN;
    float* pv_row = g_pv + b * NN;

    for (int r = 0; r < TILE_N; r++) {
        int n = n0 + r;
        int m = __ldg(mask + base + n);          // warp-uniform broadcast load
        if (!m) {
            if (lane == 0) { sc_row[n] = -1e9f; pv_row[n] = 0.0f; }
            continue;                             // skip cos work: ~50% of rows
        }
        float tv = __ldg(t + base + n);
        float sp = 0.0f, pp = 0.0f;
        const float* mr = s_mem + r * LL;
#pragma unroll
        for (int j = 0; j < 4; j++) {
            float cw = __cosf(fmaf(tv, tw[j], tc[j]));
            sp = fmaf(ckd[j], cw, sp);
            pp = fmaf(cvd[j], cw, pp);
            sp = fmaf(ckm[j], mr[j * 32 + lane], sp);
        }
#pragma unroll
        for (int o = 16; o; o >>= 1) {
            sp += __shfl_xor_sync(0xffffffffu, sp, o);
            pp += __shfl_xor_sync(0xffffffffu, pp, o);
        }
        if (lane == 0) {
            float xv = __ldg(x + base + n);
            sc_row[n] = fmaf(ck0, xv, sp) + qbk;
            pv_row[n] = pp;
        }
    }
}

// ---------------- K3: softmax + logit (1024 threads, warp reductions) -----------
__global__ void __launch_bounds__(1024) k_softmax(
        const float* __restrict__ x, float* __restrict__ out, int s) {
    __shared__ float s_red[32];
    int b = blockIdx.x, tid = threadIdx.x;
    int warp = tid >> 5, lane = tid & 31;
    const float* sc = g_scores + b * NN;
    const float* pv = g_pv + b * NN;
    long base = ((long)(s * BSZ + b)) * NN;
    float cv0 = g_cv[0];

    float mx = -3e38f;
    for (int i = tid; i < NN; i += 1024) mx = fmaxf(mx, sc[i]);
#pragma unroll
    for (int o = 16; o; o >>= 1) mx = fmaxf(mx, __shfl_xor_sync(0xffffffffu, mx, o));
    if (lane == 0) s_red[warp] = mx;
    __syncthreads();
    if (tid < 32) {
        float v = s_red[tid];
#pragma unroll
        for (int o = 16; o; o >>= 1) v = fmaxf(v, __shfl_xor_sync(0xffffffffu, v, o));
        s_red[tid] = v;
    }
    __syncthreads();
    mx = s_red[0];
    __syncthreads();

    float Z = 0.0f, V = 0.0f;
    for (int i = tid; i < NN; i += 1024) {
        float e = __expf(sc[i] - mx);
        Z += e;
        float val = fmaf(cv0, __ldg(x + base + i), g_memdot[i] + pv[i]);
        V = fmaf(e, val, V);
    }
#pragma unroll
    for (int o = 16; o; o >>= 1) {
        Z += __shfl_xor_sync(0xffffffffu, Z, o);
        V += __shfl_xor_sync(0xffffffffu, V, o);
    }
    if (lane == 0) s_red[warp] = Z;
    __syncthreads();
    if (tid < 32) {
        float v = s_red[tid];
#pragma unroll
        for (int o = 16; o; o >>= 1) v += __shfl_xor_sync(0xffffffffu, v, o);
        if (tid == 0) s_red[0] = v;
    }
    __syncthreads();
    Z = s_red[0];
    __syncthreads();
    if (lane == 0) s_red[warp] = V;
    __syncthreads();
    if (tid < 32) {
        float v = s_red[tid];
#pragma unroll
        for (int o = 16; o; o >>= 1) v += __shfl_xor_sync(0xffffffffu, v, o);
        if (tid == 0) out[s * BSZ + b] = v / Z + g_cvc;
    }
}

// ---------------- host -----------------------------------------------------------
extern "C" void kernel_launch(void* const* d_in, const int* in_sizes, int n_in,
                              void* d_out, int out_size) {
    const float* x       = (const float*)d_in[0];
    const float* t       = (const float*)d_in[1];
    const int*   src     = (const int*)d_in[2];
    const int*   tgt     = (const int*)d_in[3];
    const int*   mask    = (const int*)d_in[4];
    const float* time_w  = (const float*)d_in[5];
    const float* time_b  = (const float*)d_in[6];
    const float* W_ih    = (const float*)d_in[7];
    const float* W_hh    = (const float*)d_in[8];
    const float* b_ih    = (const float*)d_in[9];
    const float* b_hh    = (const float*)d_in[10];
    const float* Wq      = (const float*)d_in[11];
    const float* bq      = (const float*)d_in[12];
    const float* Wk      = (const float*)d_in[13];
    const float* bk      = (const float*)d_in[14];
    const float* Wv      = (const float*)d_in[15];
    const float* bv      = (const float*)d_in[16];
    const float* W_out   = (const float*)d_in[17];
    const float* b_out   = (const float*)d_in[18];
    float* out = (float*)d_out;

    k_zero_mem<<<(NN * LL + 255) / 256, 256>>>();
    k_init<<<1, 288>>>(Wv, W_out, bv, b_out, time_b);

    for (int s = 0; s < S_LEN; s++) {
        k_gru<<<128, 384>>>(x, t, src, tgt, time_w, time_b, W_ih, W_hh, b_ih, b_hh, s);
        k_scatter<<<128, 128>>>(src, tgt, s);
        k_qck<<<64, 256>>>(x, tgt, Wq, bq, Wk, bk, s);
        k_scores<<<dim3(NN / TILE_N, 8), 256>>>(x, t, mask, time_w, time_b, s);
        k_softmax<<<64, 1024>>>(x, out, s);
    }
}

// round 5
// speedup vs baseline: 2.0908x; 1.2400x over previous
#include <cuda_runtime.h>
#include <math.h>

#define S_LEN 16
#define BSZ   64
#define NN    10000
#define LL    128
#define DMSG  129
#define DH    257
#define SCALE 0.08838834764831844f  // 1/sqrt(128)
#define TILE_N 50

// ---------------- scratch --------------------------------------------------------
__device__ float g_mem[NN * LL];
__device__ int   g_dirty[NN];             // node ever written?
__device__ float g_newh[2 * BSZ * LL];
__device__ float g_ck[BSZ * DH];
__device__ float g_qbk[BSZ];
__device__ float g_scores[BSZ * NN];
__device__ float g_pv[BSZ * NN];
__device__ float g_memdot[NN];            // mem[n] . cv_mem (incremental)
__device__ float g_cv[DH];
__device__ float g_cvc;
__device__ float g_enc0[LL];

// ---------------- K0a ------------------------------------------------------------
__global__ void k_zero_mem() {
    int i = blockIdx.x * blockDim.x + threadIdx.x;
    if (i < NN * LL) g_mem[i] = 0.0f;
    if (i < NN) { g_memdot[i] = 0.0f; g_dirty[i] = 0; }
}

// ---------------- K0b ------------------------------------------------------------
__global__ void k_init(const float* __restrict__ Wv, const float* __restrict__ W_out,
                       const float* __restrict__ bv, const float* __restrict__ b_out,
                       const float* __restrict__ time_b) {
    int tid = threadIdx.x;
    if (tid < DH) {
        float a = 0.0f;
        const float* wr = Wv + tid * LL;
        for (int l = 0; l < LL; l++) a = fmaf(wr[l], W_out[l], a);
        g_cv[tid] = a;
    }
    if (tid < LL) g_enc0[tid] = cosf(time_b[tid]);
    if (tid == 280) {
        float a = 0.0f;
        for (int l = 0; l < LL; l++) a = fmaf(bv[l], W_out[l], a);
        g_cvc = a + b_out[0];
    }
}

// ---------------- K1a: GRU, 4 cells per block ------------------------------------
__global__ void __launch_bounds__(384) k_gru(
        const float* __restrict__ x, const float* __restrict__ t,
        const int* __restrict__ src, const int* __restrict__ tgt,
        const float* __restrict__ time_w, const float* __restrict__ time_b,
        const float* __restrict__ W_ih, const float* __restrict__ W_hh,
        const float* __restrict__ b_ih, const float* __restrict__ b_hh,
        int s) {
    __shared__ float s_msg[4][160];       // padded; [129..159] zero
    __shared__ float s_h[4][LL];
    __shared__ float s_sum[2 * LL * 4];
    __shared__ float s_in[LL * 4];
    __shared__ float s_hn[LL * 4];
    __shared__ int   s_node[4];

    int tid = threadIdx.x;
    int warp = tid >> 5, lane = tid & 31;

    if (tid < 4) {
        int cell = blockIdx.x * 4 + tid;
        int b = cell & 63, is_t = cell >> 6;
        s_node[tid] = (is_t ? tgt : src)[s * BSZ + b];
    }
    __syncthreads();

#pragma unroll
    for (int c = 0; c < 4; c++) {
        int cell = blockIdx.x * 4 + c;
        int b = cell & 63;
        long base = ((long)(s * BSZ + b)) * NN + s_node[c];
        if (tid < LL) {
            s_h[c][tid] = g_mem[s_node[c] * LL + tid];
            float tv = t[base];
            s_msg[c][1 + tid] = cosf(fmaf(tv, time_w[tid], time_b[tid]));
        }
        if (tid == 128) s_msg[c][0] = x[base];
        if (tid >= 129 && tid < 160) s_msg[c][tid] = 0.0f;
    }
    __syncthreads();

    for (int i = 0; i < 32; i++) {
        int j = warp + 12 * i;   // 0..383
        const float* wi = W_ih + j * DMSG;
        const float* wh = W_hh + j * LL;
        float wreg[5], hreg[4];
#pragma unroll
        for (int ch = 0; ch < 5; ch++) {
            int d = ch * 32 + lane;
            wreg[ch] = (d < DMSG) ? __ldg(wi + d) : 0.0f;
        }
#pragma unroll
        for (int ch = 0; ch < 4; ch++) hreg[ch] = __ldg(wh + ch * 32 + lane);

        float ai[4] = {0, 0, 0, 0}, ah[4] = {0, 0, 0, 0};
#pragma unroll
        for (int c = 0; c < 4; c++) {
#pragma unroll
            for (int ch = 0; ch < 5; ch++) ai[c] = fmaf(wreg[ch], s_msg[c][ch * 32 + lane], ai[c]);
#pragma unroll
            for (int ch = 0; ch < 4; ch++) ah[c] = fmaf(hreg[ch], s_h[c][ch * 32 + lane], ah[c]);
        }

        if (j < 2 * LL) {
            float v[4];
#pragma unroll
            for (int c = 0; c < 4; c++) {
                v[c] = ai[c] + ah[c];
#pragma unroll
                for (int o = 16; o; o >>= 1) v[c] += __shfl_xor_sync(0xffffffffu, v[c], o);
            }
            if (lane == 0) {
                float bb = b_ih[j] + b_hh[j];
#pragma unroll
                for (int c = 0; c < 4; c++) s_sum[j * 4 + c] = v[c] + bb;
            }
        } else {
#pragma unroll
            for (int c = 0; c < 4; c++) {
#pragma unroll
                for (int o = 16; o; o >>= 1) {
                    ai[c] += __shfl_xor_sync(0xffffffffu, ai[c], o);
                    ah[c] += __shfl_xor_sync(0xffffffffu, ah[c], o);
                }
            }
            if (lane == 0) {
                float bi = b_ih[j], bh = b_hh[j];
                int jj = j - 2 * LL;
#pragma unroll
                for (int c = 0; c < 4; c++) {
                    s_in[jj * 4 + c] = ai[c] + bi;
                    s_hn[jj * 4 + c] = ah[c] + bh;
                }
            }
        }
    }
    __syncthreads();

    if (tid < LL) {
#pragma unroll
        for (int c = 0; c < 4; c++) {
            int cell = blockIdx.x * 4 + c;
            float r = 1.0f / (1.0f + __expf(-s_sum[tid * 4 + c]));
            float z = 1.0f / (1.0f + __expf(-s_sum[(LL + tid) * 4 + c]));
            float nn = tanhf(fmaf(r, s_hn[tid * 4 + c], s_in[tid * 4 + c]));
            g_newh[cell * LL + tid] = fmaf(z, s_h[c][tid] - nn, nn);
        }
    }
}

// ---------------- K1b: scatter (winner vote) + memdot + dirty --------------------
__global__ void k_scatter(const int* __restrict__ src, const int* __restrict__ tgt, int s) {
    __shared__ int s_nodes[2 * BSZ];
    __shared__ float s_red[4];
    int c = blockIdx.x;
    int tid = threadIdx.x;  // 128

    s_nodes[tid] = (tid < BSZ) ? src[s * BSZ + tid] : tgt[s * BSZ + (tid - BSZ)];
    __syncthreads();
    int my = s_nodes[c];
    bool loser = (tid > c) && (s_nodes[tid] == my);
    if (__syncthreads_or(loser)) return;

    float v = g_newh[c * LL + tid];
    g_mem[my * LL + tid] = v;

    float a = v * g_cv[1 + tid];
#pragma unroll
    for (int o = 16; o; o >>= 1) a += __shfl_xor_sync(0xffffffffu, a, o);
    if ((tid & 31) == 0) s_red[tid >> 5] = a;
    __syncthreads();
    if (tid == 0) {
        g_memdot[my] = s_red[0] + s_red[1] + s_red[2] + s_red[3];
        g_dirty[my] = 1;
    }
}

// ---------------- K1c: q + ck ----------------------------------------------------
__global__ void __launch_bounds__(256) k_qck(
        const float* __restrict__ x, const int* __restrict__ tgt,
        const float* __restrict__ Wq, const float* __restrict__ bq,
        const float* __restrict__ Wk, const float* __restrict__ bk, int s) {
    __shared__ float s_th[DH];
    __shared__ float s_qp[2][LL];
    __shared__ float s_q[LL];
    int b = blockIdx.x;
    int tid = threadIdx.x;  // 256
    int warp = tid >> 5, lane = tid & 31;
    int node = tgt[s * BSZ + b];
    if (tid == 0) s_th[0] = x[((long)(s * BSZ + b)) * NN + node];
    if (tid < LL) {
        s_th[1 + tid] = g_mem[node * LL + tid];
        s_th[1 + LL + tid] = g_enc0[tid];
    }
    __syncthreads();
    {
        int l = tid & 127, half = tid >> 7;
        int d0 = half * 128, d1 = half ? DH : 128;
        float a0 = 0.f, a1 = 0.f, a2 = 0.f, a3 = 0.f;
        int d = d0;
        for (; d + 3 < d1; d += 4) {
            a0 = fmaf(s_th[d],     __ldg(Wq + (d    ) * LL + l), a0);
            a1 = fmaf(s_th[d + 1], __ldg(Wq + (d + 1) * LL + l), a1);
            a2 = fmaf(s_th[d + 2], __ldg(Wq + (d + 2) * LL + l), a2);
            a3 = fmaf(s_th[d + 3], __ldg(Wq + (d + 3) * LL + l), a3);
        }
        for (; d < d1; d++) a0 = fmaf(s_th[d], __ldg(Wq + d * LL + l), a0);
        s_qp[half][l] = (a0 + a1) + (a2 + a3);
    }
    __syncthreads();
    if (tid < LL) s_q[tid] = s_qp[0][tid] + s_qp[1][tid] + bq[tid];
    __syncthreads();

    for (int d = warp; d < DH; d += 8) {
        float a = 0.0f;
        const float* wr = Wk + d * LL;
#pragma unroll
        for (int ch = 0; ch < 4; ch++) a = fmaf(__ldg(wr + ch * 32 + lane), s_q[ch * 32 + lane], a);
#pragma unroll
        for (int o = 16; o; o >>= 1) a += __shfl_xor_sync(0xffffffffu, a, o);
        if (lane == 0) g_ck[b * DH + d] = SCALE * a;
    }
    if (tid == 0) {
        float a = 0.0f;
        for (int l = 0; l < LL; l++) a = fmaf(s_q[l], bk[l], a);
        g_qbk[b] = SCALE * a;
    }
}

// ---------------- K2: scores + pv (lane-staged, dirty-sparse mem) ----------------
__global__ void __launch_bounds__(256) k_scores(
        const float* __restrict__ x, const float* __restrict__ t,
        const int* __restrict__ mask,
        const float* __restrict__ time_w, const float* __restrict__ time_b, int s) {
    int tid = threadIdx.x;
    int warp = tid >> 5, lane = tid & 31;
    int n0 = blockIdx.x * TILE_N;
    int b = blockIdx.y * 8 + warp;
    long base = ((long)(s * BSZ + b)) * NN;

    // lane-staged row data (rows 0..31 in A, 32..49 in B)
    int nA = n0 + lane;
    int nB = n0 + 32 + ((lane < 18) ? lane : 17);
    float tA = __ldg(t + base + nA),  tB = __ldg(t + base + nB);
    int   mA = __ldg(mask + base + nA), mB = __ldg(mask + base + nB);
    float xA = __ldg(x + base + nA),  xB = __ldg(x + base + nB);
    int   dA = g_dirty[nA],           dB = g_dirty[nB];

    float tw[4], tc[4], ckd[4], ckm[4], cvd[4];
#pragma unroll
    for (int j = 0; j < 4; j++) {
        int l = j * 32 + lane;
        tw[j]  = time_w[l];
        tc[j]  = time_b[l];
        ckd[j] = g_ck[b * DH + 1 + LL + l];
        ckm[j] = g_ck[b * DH + 1 + l];
        cvd[j] = g_cv[1 + LL + l];
    }
    float ck0 = g_ck[b * DH];
    float qbk = g_qbk[b];

    float oScA = -1e9f, oPvA = 0.0f, oScB = -1e9f, oPvB = 0.0f;

#pragma unroll 4
    for (int r = 0; r < 32; r++) {
        int m = __shfl_sync(0xffffffffu, mA, r);
        if (!m) continue;
        float tv = __shfl_sync(0xffffffffu, tA, r);
        int dirty = __shfl_sync(0xffffffffu, dA, r);
        float sp = 0.0f, pp = 0.0f;
#pragma unroll
        for (int j = 0; j < 4; j++) {
            float cw = __cosf(fmaf(tv, tw[j], tc[j]));
            sp = fmaf(ckd[j], cw, sp);
            pp = fmaf(cvd[j], cw, pp);
        }
        if (dirty) {
            const float* mr = g_mem + (long)(n0 + r) * LL;
#pragma unroll
            for (int j = 0; j < 4; j++) sp = fmaf(ckm[j], __ldg(mr + j * 32 + lane), sp);
        }
#pragma unroll
        for (int o = 16; o; o >>= 1) {
            sp += __shfl_xor_sync(0xffffffffu, sp, o);
            pp += __shfl_xor_sync(0xffffffffu, pp, o);
        }
        if (lane == r) { oScA = fmaf(ck0, xA, sp) + qbk; oPvA = pp; }
    }
#pragma unroll 4
    for (int r = 0; r < 18; r++) {
        int m = __shfl_sync(0xffffffffu, mB, r);
        if (!m) continue;
        float tv = __shfl_sync(0xffffffffu, tB, r);
        int dirty = __shfl_sync(0xffffffffu, dB, r);
        float sp = 0.0f, pp = 0.0f;
#pragma unroll
        for (int j = 0; j < 4; j++) {
            float cw = __cosf(fmaf(tv, tw[j], tc[j]));
            sp = fmaf(ckd[j], cw, sp);
            pp = fmaf(cvd[j], cw, pp);
        }
        if (dirty) {
            const float* mr = g_mem + (long)(n0 + 32 + r) * LL;
#pragma unroll
            for (int j = 0; j < 4; j++) sp = fmaf(ckm[j], __ldg(mr + j * 32 + lane), sp);
        }
#pragma unroll
        for (int o = 16; o; o >>= 1) {
            sp += __shfl_xor_sync(0xffffffffu, sp, o);
            pp += __shfl_xor_sync(0xffffffffu, pp, o);
        }
        if (lane == r) { oScB = fmaf(ck0, xB, sp) + qbk; oPvB = pp; }
    }

    float* sc_row = g_scores + b * NN;
    float* pv_row = g_pv + b * NN;
    sc_row[n0 + lane] = oScA;
    pv_row[n0 + lane] = oPvA;
    if (lane < 18) {
        sc_row[n0 + 32 + lane] = oScB;
        pv_row[n0 + 32 + lane] = oPvB;
    }
}

// ---------------- K3: softmax + logit --------------------------------------------
__global__ void __launch_bounds__(1024) k_softmax(
        const float* __restrict__ x, float* __restrict__ out, int s) {
    __shared__ float s_red[32];
    int b = blockIdx.x, tid = threadIdx.x;
    int warp = tid >> 5, lane = tid & 31;
    const float* sc = g_scores + b * NN;
    const float* pv = g_pv + b * NN;
    long base = ((long)(s * BSZ + b)) * NN;
    float cv0 = g_cv[0];

    float mx = -3e38f;
    for (int i = tid; i < NN; i += 1024) mx = fmaxf(mx, sc[i]);
#pragma unroll
    for (int o = 16; o; o >>= 1) mx = fmaxf(mx, __shfl_xor_sync(0xffffffffu, mx, o));
    if (lane == 0) s_red[warp] = mx;
    __syncthreads();
    if (tid < 32) {
        float v = s_red[tid];
#pragma unroll
        for (int o = 16; o; o >>= 1) v = fmaxf(v, __shfl_xor_sync(0xffffffffu, v, o));
        s_red[tid] = v;
    }
    __syncthreads();
    mx = s_red[0];
    __syncthreads();

    float Z = 0.0f, V = 0.0f;
    for (int i = tid; i < NN; i += 1024) {
        float e = __expf(sc[i] - mx);
        Z += e;
        float val = fmaf(cv0, __ldg(x + base + i), g_memdot[i] + pv[i]);
        V = fmaf(e, val, V);
    }
#pragma unroll
    for (int o = 16; o; o >>= 1) {
        Z += __shfl_xor_sync(0xffffffffu, Z, o);
        V += __shfl_xor_sync(0xffffffffu, V, o);
    }
    if (lane == 0) s_red[warp] = Z;
    __syncthreads();
    if (tid < 32) {
        float v = s_red[tid];
#pragma unroll
        for (int o = 16; o; o >>= 1) v += __shfl_xor_sync(0xffffffffu, v, o);
        if (tid == 0) s_red[0] = v;
    }
    __syncthreads();
    Z = s_red[0];
    __syncthreads();
    if (lane == 0) s_red[warp] = V;
    __syncthreads();
    if (tid < 32) {
        float v = s_red[tid];
#pragma unroll
        for (int o = 16; o; o >>= 1) v += __shfl_xor_sync(0xffffffffu, v, o);
        if (tid == 0) out[s * BSZ + b] = v / Z + g_cvc;
    }
}

// ---------------- host -----------------------------------------------------------
extern "C" void kernel_launch(void* const* d_in, const int* in_sizes, int n_in,
                              void* d_out, int out_size) {
    const float* x       = (const float*)d_in[0];
    const float* t       = (const float*)d_in[1];
    const int*   src     = (const int*)d_in[2];
    const int*   tgt     = (const int*)d_in[3];
    const int*   mask    = (const int*)d_in[4];
    const float* time_w  = (const float*)d_in[5];
    const float* time_b  = (const float*)d_in[6];
    const float* W_ih    = (const float*)d_in[7];
    const float* W_hh    = (const float*)d_in[8];
    const float* b_ih    = (const float*)d_in[9];
    const float* b_hh    = (const float*)d_in[10];
    const float* Wq      = (const float*)d_in[11];
    const float* bq      = (const float*)d_in[12];
    const float* Wk      = (const float*)d_in[13];
    const float* bk      = (const float*)d_in[14];
    const float* Wv      = (const float*)d_in[15];
    const float* bv      = (const float*)d_in[16];
    const float* W_out   = (const float*)d_in[17];
    const float* b_out   = (const float*)d_in[18];
    float* out = (float*)d_out;

    k_zero_mem<<<(NN * LL + 255) / 256, 256>>>();
    k_init<<<1, 288>>>(Wv, W_out, bv, b_out, time_b);

    for (int s = 0; s < S_LEN; s++) {
        k_gru<<<32, 384>>>(x, t, src, tgt, time_w, time_b, W_ih, W_hh, b_ih, b_hh, s);
        k_scatter<<<128, 128>>>(src, tgt, s);
        k_qck<<<64, 256>>>(x, tgt, Wq, bq, Wk, bk, s);
        k_scores<<<dim3(NN / TILE_N, 8), 256>>>(x, t, mask, time_w, time_b, s);
        k_softmax<<<64, 1024>>>(x, out, s);
    }
}